// round 1
// baseline (speedup 1.0000x reference)
#include <cuda_runtime.h>

#define C_IN  128
#define H_IN  56
#define W_IN  56
#define K_OUT 256
#define N_IMG 32
#define CRS   (C_IN * 9)   // 1152

#define BK  64   // output channels per block
#define CB  8    // input channels per smem chunk
#define XSW 13   // smem row stride for X patch (conflict-free)

// Pre-quantized, transposed weights: [(c*9 + r*3 + s)][k]  -> coalesced in k
__device__ float g_wq[CRS * K_OUT];

// Quantize to s16 fixed point, 12 frac bits. jnp.round == round-half-to-even == rintf.
__device__ __forceinline__ float quant16f(float v) {
    float r = rintf(v * 4096.0f);
    r = fminf(fmaxf(r, -32768.0f), 32767.0f);
    return r * (1.0f / 4096.0f);
}

__device__ __forceinline__ unsigned long long pk2(float a, float b) {
    unsigned long long r;
    asm("mov.b64 %0, {%1, %2};" : "=l"(r) : "f"(a), "f"(b));
    return r;
}

__device__ __forceinline__ float2 up2(unsigned long long v) {
    float2 f;
    asm("mov.b64 {%0, %1}, %2;" : "=f"(f.x), "=f"(f.y) : "l"(v));
    return f;
}

// Packed dual-FMA (sm_100+): d.{lo,hi} += a.{lo,hi} * b.{lo,hi}
__device__ __forceinline__ void ffma2(unsigned long long& d,
                                      unsigned long long a,
                                      unsigned long long b) {
    asm("fma.rn.f32x2 %0, %1, %2, %0;" : "+l"(d) : "l"(a), "l"(b));
}

// One-time: quantize + transpose weights into g_wq.
__global__ void quantw_kernel(const float* __restrict__ w) {
    int idx = blockIdx.x * blockDim.x + threadIdx.x;
    if (idx >= K_OUT * CRS) return;
    int k   = idx & (K_OUT - 1);
    int crs = idx >> 8;
    g_wq[crs * K_OUT + k] = quant16f(w[k * CRS + crs]);
}

// Block: 64 k  x  8x8 spatial  x  1 image. 256 threads.
// Thread: 4 k x 1 row x 4 cols (cols packed in f32x2 pairs).
__global__ __launch_bounds__(256) void conv_kernel(const float* __restrict__ x,
                                                   float* __restrict__ out) {
    __shared__ float Ws[CB * 9 * BK];        // [(c*9 + rs)*64 + kk]
    __shared__ float Xs[CB][10][XSW];        // 10x10 patch, padded rows

    const int tid = threadIdx.x;
    const int bx  = blockIdx.x;              // 0..48 spatial tiles
    const int h0  = (bx / 7) * 8;
    const int w0  = (bx % 7) * 8;
    const int k0  = blockIdx.y * BK;
    const int n   = blockIdx.z;

    const int kt  = tid >> 4;                // 0..15  -> k group of 4
    const int pt  = tid & 15;
    const int ph  = pt >> 1;                 // 0..7   -> output row in tile
    const int pw0 = (pt & 1) * 4;            // 0 or 4 -> output col group

    unsigned long long acc[4][2];
    #pragma unroll
    for (int k = 0; k < 4; k++) { acc[k][0] = 0ull; acc[k][1] = 0ull; }

    const float* xn = x + (size_t)n * C_IN * H_IN * W_IN;

    for (int ci = 0; ci < C_IN / CB; ci++) {
        const int c0 = ci * CB;

        // --- stage weights: coalesced gmem read, conflict-free smem write ---
        #pragma unroll
        for (int i = tid; i < CB * 9 * BK; i += 256) {
            int kk = i & (BK - 1);
            int q  = i >> 6;                 // 0..71 = c*9 + rs
            Ws[i] = g_wq[(c0 * 9 + q) * K_OUT + k0 + kk];
        }

        // --- stage input patch (quantize on load, zero-pad borders) ---
        for (int i = tid; i < CB * 100; i += 256) {
            int c   = i / 100;
            int rem = i - c * 100;
            int r   = rem / 10;
            int cc  = rem - r * 10;
            int gh  = h0 - 1 + r;
            int gw  = w0 - 1 + cc;
            float v = 0.0f;
            if ((unsigned)gh < H_IN && (unsigned)gw < W_IN)
                v = quant16f(xn[((c0 + c) * H_IN + gh) * W_IN + gw]);
            Xs[c][r][cc] = v;
        }
        __syncthreads();

        // --- compute: 8c x 3r x 3s, 4k x 4cols per thread, f32x2 packed ---
        #pragma unroll
        for (int c = 0; c < CB; c++) {
            #pragma unroll
            for (int r = 0; r < 3; r++) {
                float xv[6];
                #pragma unroll
                for (int i = 0; i < 6; i++) xv[i] = Xs[c][ph + r][pw0 + i];
                #pragma unroll
                for (int s = 0; s < 3; s++) {
                    unsigned long long a0 = pk2(xv[s],     xv[s + 1]);
                    unsigned long long a1 = pk2(xv[s + 2], xv[s + 3]);
                    const float4 wv =
                        *(const float4*)&Ws[(c * 9 + r * 3 + s) * BK + kt * 4];
                    unsigned long long wx = pk2(wv.x, wv.x);
                    unsigned long long wy = pk2(wv.y, wv.y);
                    unsigned long long wz = pk2(wv.z, wv.z);
                    unsigned long long wwp = pk2(wv.w, wv.w);
                    ffma2(acc[0][0], a0, wx);  ffma2(acc[0][1], a1, wx);
                    ffma2(acc[1][0], a0, wy);  ffma2(acc[1][1], a1, wy);
                    ffma2(acc[2][0], a0, wz);  ffma2(acc[2][1], a1, wz);
                    ffma2(acc[3][0], a0, wwp); ffma2(acc[3][1], a1, wwp);
                }
            }
        }
        __syncthreads();
    }

    // --- epilogue: float2 stores, fully in-bounds (56 = 7*8) ---
    #pragma unroll
    for (int k = 0; k < 4; k++) {
        float* o = out + (((size_t)(n * K_OUT + k0 + kt * 4 + k) * H_IN
                           + (h0 + ph)) * W_IN + (w0 + pw0));
        *(float2*)(o)     = up2(acc[k][0]);
        *(float2*)(o + 2) = up2(acc[k][1]);
    }
}

extern "C" void kernel_launch(void* const* d_in, const int* in_sizes, int n_in,
                              void* d_out, int out_size) {
    const float* x = (const float*)d_in[0];
    const float* w = (const float*)d_in[1];
    float* out     = (float*)d_out;

    quantw_kernel<<<(K_OUT * CRS + 255) / 256, 256>>>(w);

    dim3 grid(49, K_OUT / BK, N_IMG);
    conv_kernel<<<grid, 256>>>(x, out);
}

// round 4
// speedup vs baseline: 1.7507x; 1.7507x over previous
#include <cuda_runtime.h>
#include <cuda_bf16.h>
#include <cstdint>

#define H_IN 56
#define W_IN 56
#define HW   3136
#define C_IN 128
#define KOUT 256
#define NIMG 32
#define PTOT (NIMG*HW)      // 100352
#define MTILES (PTOT/128)   // 784
#define KSLOT 384           // 128 channels x 3 slots (xh,xl,xh)/(wh,wh,wl)
#define NCHUNK 54           // 9 rs x 6 chunks of 64 slots

// 3-slot interleaved bf16 scratch
__device__ __align__(128) __nv_bfloat16 g_x[(size_t)PTOT * KSLOT];      // [p][3c+s]
__device__ __align__(128) __nv_bfloat16 g_w[(size_t)9 * KOUT * KSLOT];  // [rs][k][3c+s]

__device__ __forceinline__ float quant16f(float v) {
    float r = rintf(v * 4096.0f);
    r = fminf(fmaxf(r, -32768.0f), 32767.0f);
    return r * (1.0f / 4096.0f);
}

__device__ __forceinline__ uint32_t su32(const void* p) {
    uint32_t a;
    asm("{ .reg .u64 t; cvta.to.shared.u64 t, %1; cvt.u32.u64 %0, t; }"
        : "=r"(a) : "l"(p));
    return a;
}

// ---------------- pre-kernels ----------------
__global__ void prep_x(const float* __restrict__ x) {
    __shared__ __nv_bfloat16 sh[32][36];
    __shared__ __nv_bfloat16 sl[32][36];
    int w0 = blockIdx.x * 32;
    int h  = blockIdx.y;
    int n  = blockIdx.z >> 2;
    int c0 = (blockIdx.z & 3) * 32;
    int wi = threadIdx.x & 31, ci = threadIdx.x >> 5;
    int wlim = min(32, W_IN - w0);
    #pragma unroll
    for (int it = 0; it < 4; it++) {
        int cc = ci + it * 8;
        if (wi < wlim) {
            float q = quant16f(x[(((size_t)n * C_IN + c0 + cc) * H_IN + h) * W_IN + w0 + wi]);
            __nv_bfloat16 hi = __float2bfloat16(q);
            sh[cc][wi] = hi;
            sl[cc][wi] = __float2bfloat16(q - __bfloat162float(hi));
        }
    }
    __syncthreads();
    int cj = threadIdx.x & 31, wb = threadIdx.x >> 5;
    #pragma unroll
    for (int it = 0; it < 4; it++) {
        int wt = wb + it * 8;
        if (wt < wlim) {
            size_t o = ((size_t)n * HW + (size_t)h * W_IN + w0 + wt) * KSLOT
                       + 3 * (c0 + cj);
            __nv_bfloat16 hi = sh[cj][wt];
            g_x[o]     = hi;
            g_x[o + 1] = sl[cj][wt];
            g_x[o + 2] = hi;
        }
    }
}

__global__ void prep_w(const float* __restrict__ w) {
    int idx = blockIdx.x * 256 + threadIdx.x;
    if (idx >= 9 * KOUT * C_IN) return;
    int rs = idx >> 15;            // /(256*128)
    int k  = (idx >> 7) & 255;
    int c  = idx & 127;
    float q = quant16f(w[(size_t)k * 1152 + c * 9 + rs]);
    __nv_bfloat16 hi = __float2bfloat16(q);
    size_t o = ((size_t)(rs * KOUT + k)) * KSLOT + 3 * c;
    g_w[o]     = hi;
    g_w[o + 1] = hi;
    g_w[o + 2] = __float2bfloat16(q - __bfloat162float(hi));
}

// ---------------- main kernel ----------------
// smem: 4 stages x (A 16KB + B 16KB). A rows: 128 pixels x 128B (64 slots).
// B rows: 128 kout x 128B. group swizzle: grp ^= (row & 7).
#define A_ST(s) ((s) * 16384u)
#define B_ST(s) (65536u + (s) * 16384u)
#define SMEM_TOTAL 131072

__device__ __forceinline__ void cp16(uint32_t dst, const void* src, uint32_t ssz) {
    asm volatile("cp.async.cg.shared.global [%0], [%1], 16, %2;"
                 :: "r"(dst), "l"(src), "r"(ssz) : "memory");
}

__device__ __forceinline__ void ldsm4(uint32_t* r, uint32_t addr) {
    asm volatile("ldmatrix.sync.aligned.m8n8.x4.shared.b16 {%0,%1,%2,%3}, [%4];"
                 : "=r"(r[0]), "=r"(r[1]), "=r"(r[2]), "=r"(r[3]) : "r"(addr));
}

__device__ __forceinline__ void mma16816(float* c, const uint32_t* a,
                                         uint32_t b0, uint32_t b1) {
    asm volatile(
        "mma.sync.aligned.m16n8k16.row.col.f32.bf16.bf16.f32 "
        "{%0,%1,%2,%3}, {%4,%5,%6,%7}, {%8,%9}, {%0,%1,%2,%3};"
        : "+f"(c[0]), "+f"(c[1]), "+f"(c[2]), "+f"(c[3])
        : "r"(a[0]), "r"(a[1]), "r"(a[2]), "r"(a[3]), "r"(b0), "r"(b1));
}

__global__ __launch_bounds__(256, 1) void conv_mma(float* __restrict__ out) {
    extern __shared__ char smem[];
    const uint32_t sb = su32(smem);
    const int tid = threadIdx.x;
    const int wid = tid >> 5, lane = tid & 31;
    const int wm = wid & 1, wn = wid >> 1;         // warp tile: 64m x 32n
    const unsigned p0 = blockIdx.x << 7;
    const int n0 = blockIdx.y << 7;

    // per-thread cp.async coords: row = tid>>1, 64B half = tid&1
    const int rowT = tid >> 1, half = tid & 1;
    const unsigned p = p0 + rowT;
    const unsigned nImg = p / 3136u;
    const unsigned rem = p - nImg * 3136u;
    const int hh = (int)(rem / 56u);
    const int ww = (int)(rem - (unsigned)hh * 56u);

    float acc[4][4][4];
    #pragma unroll
    for (int i = 0; i < 4; i++)
        #pragma unroll
        for (int j = 0; j < 4; j++)
            #pragma unroll
            for (int k = 0; k < 4; k++) acc[i][j][k] = 0.0f;

    // ---- stage issue: chunk t -> rs = t/6, slot0 = (t%6)*64, stage = t&3
    auto issue = [&](int t) {
        const int st = t & 3;
        const int rs = t / 6;
        const int slot0 = (t - rs * 6) << 6;
        const int r = rs / 3, s = rs - 3 * r;
        const int gh = hh + r - 1, gw = ww + s - 1;
        const bool valid = ((unsigned)gh < H_IN) && ((unsigned)gw < W_IN);
        const int ghc = valid ? gh : hh, gwc = valid ? gw : ww;  // clamped addr
        const uint32_t ssz = valid ? 16u : 0u;
        const __nv_bfloat16* asrc =
            g_x + ((size_t)(nImg * 3136u + (unsigned)(ghc * 56 + gwc))) * KSLOT
                + slot0 + half * 32;
        const __nv_bfloat16* bsrc =
            g_w + ((size_t)(rs * KOUT + n0 + rowT)) * KSLOT + slot0 + half * 32;
        #pragma unroll
        for (int j = 0; j < 4; j++) {
            const uint32_t g = half * 4 + j;
            const uint32_t sw = (g ^ (rowT & 7)) << 4;
            cp16(sb + A_ST(st) + rowT * 128 + sw, asrc + j * 8, ssz);
            cp16(sb + B_ST(st) + rowT * 128 + sw, bsrc + j * 8, 16u);
        }
        asm volatile("cp.async.commit_group;" ::: "memory");
    };

    issue(0); issue(1); issue(2);

    for (int t = 0; t < NCHUNK; t++) {
        asm volatile("cp.async.wait_group 2;" ::: "memory");
        __syncthreads();
        if (t + 3 < NCHUNK) issue(t + 3);
        else asm volatile("cp.async.commit_group;" ::: "memory");  // keep count aligned

        const uint32_t Ab = sb + A_ST(t & 3);
        const uint32_t Bb = sb + B_ST(t & 3);
        #pragma unroll
        for (int stp = 0; stp < 4; stp++) {
            uint32_t ar[4][4], br[2][4];
            #pragma unroll
            for (int mt = 0; mt < 4; mt++) {
                const int row = wm * 64 + mt * 16 + (lane & 7) + ((lane >> 3) & 1) * 8;
                const int grp = 2 * stp + (lane >> 4);
                ldsm4(ar[mt], Ab + row * 128 + ((grp ^ (row & 7)) << 4));
            }
            #pragma unroll
            for (int bt = 0; bt < 2; bt++) {
                const int row = wn * 32 + bt * 16 + (lane & 7) + (lane >> 4) * 8;
                const int grp = 2 * stp + ((lane >> 3) & 1);
                ldsm4(br[bt], Bb + row * 128 + ((grp ^ (row & 7)) << 4));
            }
            #pragma unroll
            for (int mt = 0; mt < 4; mt++)
                #pragma unroll
                for (int nt = 0; nt < 4; nt++)
                    mma16816(acc[mt][nt], ar[mt],
                             br[nt >> 1][(nt & 1) * 2], br[nt >> 1][(nt & 1) * 2 + 1]);
        }
        __syncthreads();
    }

    // ---- epilogue: accum -> smem [n][m] -> coalesced float4 stores ----
    float* eb = (float*)smem;
    {
        const int r = lane >> 2, c = (lane & 3) * 2;
        #pragma unroll
        for (int mt = 0; mt < 4; mt++)
            #pragma unroll
            for (int nt = 0; nt < 4; nt++) {
                const int m = wm * 64 + mt * 16 + r;
                const int n = wn * 32 + nt * 8 + c;
                eb[n * 132 + m]           = acc[mt][nt][0];
                eb[(n + 1) * 132 + m]     = acc[mt][nt][1];
                eb[n * 132 + m + 8]       = acc[mt][nt][2];
                eb[(n + 1) * 132 + m + 8] = acc[mt][nt][3];
            }
    }
    __syncthreads();
    for (int j = tid; j < 4096; j += 256) {
        const int nr = j >> 5;
        const int m4 = (j & 31) << 2;
        const unsigned pp = p0 + m4;
        const unsigned ni = pp / 3136u;
        const unsigned hw = pp - ni * 3136u;
        const float4 v = *(const float4*)&eb[nr * 132 + m4];
        *(float4*)(out + ((size_t)(ni * KOUT + n0 + nr)) * HW + hw) = v;
    }
}

extern "C" void kernel_launch(void* const* d_in, const int* in_sizes, int n_in,
                              void* d_out, int out_size) {
    const float* x = (const float*)d_in[0];
    const float* w = (const float*)d_in[1];
    float* out = (float*)d_out;

    cudaFuncSetAttribute(conv_mma, cudaFuncAttributeMaxDynamicSharedMemorySize,
                         SMEM_TOTAL);

    dim3 gx(2, 56, 128);
    prep_x<<<gx, 256>>>(x);
    prep_w<<<(9 * KOUT * C_IN + 255) / 256, 256>>>(w);
    dim3 grid(MTILES, KOUT / 128, 1);
    conv_mma<<<grid, 256, SMEM_TOTAL>>>(out);
}

// round 5
// speedup vs baseline: 4.7969x; 2.7400x over previous
#include <cuda_runtime.h>
#include <cuda_fp16.h>
#include <cstdint>

#define H_IN 56
#define W_IN 56
#define HW   3136
#define C_IN 128
#define KOUT 256
#define NIMG 32
#define PTOT (NIMG*HW)      // 100352
#define MTILES (PTOT/128)   // 784
#define NCHUNK 18           // 9 rs x 2 chunks of 64 channels

// fp16 scratch: quantized values are exactly representable (weights always,
// x whenever |x|<0.5; else <=2^-11 rel rounding -> ~2e-4 output rel_err)
__device__ __align__(128) __half g_x[(size_t)PTOT * C_IN];        // [p][c]
__device__ __align__(128) __half g_w[(size_t)9 * KOUT * C_IN];    // [rs][k][c]

__device__ __forceinline__ float quant16f(float v) {
    float r = rintf(v * 4096.0f);
    r = fminf(fmaxf(r, -32768.0f), 32767.0f);
    return r * (1.0f / 4096.0f);
}

__device__ __forceinline__ uint32_t su32(const void* p) {
    uint32_t a;
    asm("{ .reg .u64 t; cvta.to.shared.u64 t, %1; cvt.u32.u64 %0, t; }"
        : "=r"(a) : "l"(p));
    return a;
}

// ---------------- pre-kernels ----------------
__global__ void prep_x(const float* __restrict__ x) {
    __shared__ __half sh[32][36];
    int w0 = blockIdx.x * 32;
    int h  = blockIdx.y;
    int n  = blockIdx.z >> 2;
    int c0 = (blockIdx.z & 3) * 32;
    int wi = threadIdx.x & 31, ci = threadIdx.x >> 5;
    int wlim = min(32, W_IN - w0);
    #pragma unroll
    for (int it = 0; it < 4; it++) {
        int cc = ci + it * 8;
        if (wi < wlim) {
            float q = quant16f(x[(((size_t)n * C_IN + c0 + cc) * H_IN + h) * W_IN + w0 + wi]);
            sh[cc][wi] = __float2half(q);
        }
    }
    __syncthreads();
    int cj = threadIdx.x & 31, wb = threadIdx.x >> 5;
    #pragma unroll
    for (int it = 0; it < 4; it++) {
        int wt = wb + it * 8;
        if (wt < wlim)
            g_x[((size_t)n * HW + (size_t)h * W_IN + w0 + wt) * C_IN + c0 + cj] =
                sh[cj][wt];
    }
}

__global__ void prep_w(const float* __restrict__ w) {
    int idx = blockIdx.x * 256 + threadIdx.x;
    if (idx >= 9 * KOUT * C_IN) return;
    int rs = idx >> 15;            // /(256*128)
    int k  = (idx >> 7) & 255;
    int c  = idx & 127;
    float q = quant16f(w[(size_t)k * 1152 + c * 9 + rs]);
    g_w[(size_t)(rs * KOUT + k) * C_IN + c] = __float2half(q);
}

// ---------------- main kernel ----------------
// smem: 4 stages x (A 16KB + B 16KB). A rows: 128 pixels x 128B (64 ch).
// B rows: 128 kout x 128B. group swizzle: grp ^= (row & 7).
#define A_ST(s) ((s) * 16384u)
#define B_ST(s) (65536u + (s) * 16384u)
#define SMEM_TOTAL 131072

__device__ __forceinline__ void cp16(uint32_t dst, const void* src, uint32_t ssz) {
    asm volatile("cp.async.cg.shared.global [%0], [%1], 16, %2;"
                 :: "r"(dst), "l"(src), "r"(ssz) : "memory");
}

__device__ __forceinline__ void ldsm4(uint32_t* r, uint32_t addr) {
    asm volatile("ldmatrix.sync.aligned.m8n8.x4.shared.b16 {%0,%1,%2,%3}, [%4];"
                 : "=r"(r[0]), "=r"(r[1]), "=r"(r[2]), "=r"(r[3]) : "r"(addr));
}

__device__ __forceinline__ void mma16816(float* c, const uint32_t* a,
                                         uint32_t b0, uint32_t b1) {
    asm volatile(
        "mma.sync.aligned.m16n8k16.row.col.f32.f16.f16.f32 "
        "{%0,%1,%2,%3}, {%4,%5,%6,%7}, {%8,%9}, {%0,%1,%2,%3};"
        : "+f"(c[0]), "+f"(c[1]), "+f"(c[2]), "+f"(c[3])
        : "r"(a[0]), "r"(a[1]), "r"(a[2]), "r"(a[3]), "r"(b0), "r"(b1));
}

__global__ __launch_bounds__(256, 1) void conv_mma(float* __restrict__ out) {
    extern __shared__ char smem[];
    const uint32_t sb = su32(smem);
    const int tid = threadIdx.x;
    const int wid = tid >> 5, lane = tid & 31;
    const int wm = wid & 1, wn = wid >> 1;         // warp tile: 64m x 32n
    const unsigned p0 = blockIdx.x << 7;
    const int n0 = blockIdx.y << 7;

    // per-thread cp.async coords: row = tid>>1, 64B half = tid&1
    const int rowT = tid >> 1, half = tid & 1;
    const unsigned p = p0 + rowT;
    const unsigned nImg = p / 3136u;
    const unsigned rem = p - nImg * 3136u;
    const int hh = (int)(rem / 56u);
    const int ww = (int)(rem - (unsigned)hh * 56u);

    float acc[4][4][4];
    #pragma unroll
    for (int i = 0; i < 4; i++)
        #pragma unroll
        for (int j = 0; j < 4; j++)
            #pragma unroll
            for (int k = 0; k < 4; k++) acc[i][j][k] = 0.0f;

    // ---- stage issue: chunk t -> rs = t>>1, ch0 = (t&1)*64, stage = t&3
    auto issue = [&](int t) {
        const int st = t & 3;
        const int rs = t >> 1;
        const int ch0 = (t & 1) << 6;
        const int r = rs / 3, s = rs - 3 * r;
        const int gh = hh + r - 1, gw = ww + s - 1;
        const bool valid = ((unsigned)gh < H_IN) && ((unsigned)gw < W_IN);
        const int ghc = valid ? gh : hh, gwc = valid ? gw : ww;  // clamped addr
        const uint32_t ssz = valid ? 16u : 0u;
        const __half* asrc =
            g_x + ((size_t)(nImg * 3136u + (unsigned)(ghc * 56 + gwc))) * C_IN
                + ch0 + half * 32;
        const __half* bsrc =
            g_w + ((size_t)(rs * KOUT + n0 + rowT)) * C_IN + ch0 + half * 32;
        #pragma unroll
        for (int j = 0; j < 4; j++) {
            const uint32_t g = half * 4 + j;
            const uint32_t sw = (g ^ (rowT & 7)) << 4;
            cp16(sb + A_ST(st) + rowT * 128 + sw, asrc + j * 8, ssz);
            cp16(sb + B_ST(st) + rowT * 128 + sw, bsrc + j * 8, 16u);
        }
        asm volatile("cp.async.commit_group;" ::: "memory");
    };

    issue(0); issue(1); issue(2);

    for (int t = 0; t < NCHUNK; t++) {
        asm volatile("cp.async.wait_group 2;" ::: "memory");
        __syncthreads();
        if (t + 3 < NCHUNK) issue(t + 3);
        else asm volatile("cp.async.commit_group;" ::: "memory");  // keep count aligned

        const uint32_t Ab = sb + A_ST(t & 3);
        const uint32_t Bb = sb + B_ST(t & 3);
        #pragma unroll
        for (int stp = 0; stp < 4; stp++) {
            uint32_t ar[4][4], br[2][4];
            #pragma unroll
            for (int mt = 0; mt < 4; mt++) {
                const int row = wm * 64 + mt * 16 + (lane & 7) + ((lane >> 3) & 1) * 8;
                const int grp = 2 * stp + (lane >> 4);
                ldsm4(ar[mt], Ab + row * 128 + ((grp ^ (row & 7)) << 4));
            }
            #pragma unroll
            for (int bt = 0; bt < 2; bt++) {
                const int row = wn * 32 + bt * 16 + (lane & 7) + (lane >> 4) * 8;
                const int grp = 2 * stp + ((lane >> 3) & 1);
                ldsm4(br[bt], Bb + row * 128 + ((grp ^ (row & 7)) << 4));
            }
            #pragma unroll
            for (int mt = 0; mt < 4; mt++)
                #pragma unroll
                for (int nt = 0; nt < 4; nt++)
                    mma16816(acc[mt][nt], ar[mt],
                             br[nt >> 1][(nt & 1) * 2], br[nt >> 1][(nt & 1) * 2 + 1]);
        }
        __syncthreads();
    }

    // ---- epilogue: accum -> smem [n][m] -> coalesced float4 stores ----
    float* eb = (float*)smem;
    {
        const int r = lane >> 2, c = (lane & 3) * 2;
        #pragma unroll
        for (int mt = 0; mt < 4; mt++)
            #pragma unroll
            for (int nt = 0; nt < 4; nt++) {
                const int m = wm * 64 + mt * 16 + r;
                const int n = wn * 32 + nt * 8 + c;
                eb[n * 132 + m]           = acc[mt][nt][0];
                eb[(n + 1) * 132 + m]     = acc[mt][nt][1];
                eb[n * 132 + m + 8]       = acc[mt][nt][2];
                eb[(n + 1) * 132 + m + 8] = acc[mt][nt][3];
            }
    }
    __syncthreads();
    for (int j = tid; j < 4096; j += 256) {
        const int nr = j >> 5;
        const int m4 = (j & 31) << 2;
        const unsigned pp = p0 + m4;
        const unsigned ni = pp / 3136u;
        const unsigned hw = pp - ni * 3136u;
        const float4 v = *(const float4*)&eb[nr * 132 + m4];
        *(float4*)(out + ((size_t)(ni * KOUT + n0 + nr)) * HW + hw) = v;
    }
}

extern "C" void kernel_launch(void* const* d_in, const int* in_sizes, int n_in,
                              void* d_out, int out_size) {
    const float* x = (const float*)d_in[0];
    const float* w = (const float*)d_in[1];
    float* out = (float*)d_out;

    cudaFuncSetAttribute(conv_mma, cudaFuncAttributeMaxDynamicSharedMemorySize,
                         SMEM_TOTAL);

    dim3 gx(2, 56, 128);
    prep_x<<<gx, 256>>>(x);
    prep_w<<<(9 * KOUT * C_IN + 255) / 256, 256>>>(w);
    dim3 grid(MTILES, KOUT / 128, 1);
    conv_mma<<<grid, 256, SMEM_TOTAL>>>(out);
}

// round 6
// speedup vs baseline: 5.2038x; 1.0848x over previous
#include <cuda_runtime.h>
#include <cuda_fp16.h>
#include <cstdint>

#define H_IN 56
#define W_IN 56
#define C_IN 128
#define KOUT 256
#define NIMG 32
#define W2   28                      // output-pair columns
#define P2TOT (NIMG*H_IN*W2)         // 50176 GEMM rows
#define P2IMG (H_IN*W2)              // 1568
#define VSTRIDE ((size_t)P2TOT*C_IN) // per-t V plane
#define NCHUNK 24                    // 4 GEMMs x 3 r x 2 c-halves

// Winograd-transformed scratch
__device__ __align__(128) __half g_v[4 * VSTRIDE];            // [t][p2][c]
__device__ __align__(128) __half g_u[4 * 3 * KOUT * C_IN];    // [t][r][k][c]

__constant__ int c_ord[4] = {0, 3, 1, 2};   // GEMM processing order -> t

__device__ __forceinline__ float quant16f(float v) {
    float r = rintf(v * 4096.0f);
    r = fminf(fmaxf(r, -32768.0f), 32767.0f);
    return r * (1.0f / 4096.0f);
}

__device__ __forceinline__ uint32_t su32(const void* p) {
    uint32_t a;
    asm("{ .reg .u64 t; cvta.to.shared.u64 t, %1; cvt.u32.u64 %0, t; }"
        : "=r"(a) : "l"(p));
    return a;
}

// ---------------- pre-kernels ----------------
// V transform: one (n,h) row, all 128 c. d_s = qx[w=2*w2-1+s] (zero-padded).
__global__ void prep_xw(const float* __restrict__ x) {
    __shared__ __half xs[C_IN][58];   // [c][w+1], w=-1..56
    const int h = blockIdx.x;
    const int n = blockIdx.y;
    const int tid = threadIdx.x;

    for (int i = tid; i < C_IN * W_IN; i += 256) {
        int c = i / W_IN, w = i - c * W_IN;
        xs[c][w + 1] = __float2half(
            quant16f(x[(((size_t)n * C_IN + c) * H_IN + h) * W_IN + w]));
    }
    if (tid < C_IN) { xs[tid][0] = __float2half(0.f); xs[tid][57] = __float2half(0.f); }
    __syncthreads();

    const size_t pbase = ((size_t)(n * H_IN + h) * W2) * C_IN;
    for (int j = tid; j < W2 * C_IN; j += 256) {
        int c = j & 127, w2 = j >> 7;
        float d0 = __half2float(xs[c][2 * w2]);
        float d1 = __half2float(xs[c][2 * w2 + 1]);
        float d2 = __half2float(xs[c][2 * w2 + 2]);
        float d3 = __half2float(xs[c][2 * w2 + 3]);
        size_t o = pbase + (size_t)w2 * C_IN + c;
        g_v[o]               = __float2half(d0 - d2);
        g_v[VSTRIDE + o]     = __float2half(d1 + d2);
        g_v[2 * VSTRIDE + o] = __float2half(d2 - d1);
        g_v[3 * VSTRIDE + o] = __float2half(d1 - d3);
    }
}

// U transform: [t][r][k][c]; t=3 negated so y1 accumulates -m3 directly.
__global__ void prep_wu(const float* __restrict__ w) {
    int idx = blockIdx.x * 256 + threadIdx.x;
    if (idx >= 4 * 3 * KOUT * C_IN) return;
    int t = idx / (3 * KOUT * C_IN);
    int r = (idx / (KOUT * C_IN)) % 3;
    int k = (idx >> 7) & 255;
    int c = idx & 127;
    const float* gp = w + (size_t)k * 1152 + c * 9 + r * 3;
    float g0 = quant16f(gp[0]), g1 = quant16f(gp[1]), g2 = quant16f(gp[2]);
    float u;
    if (t == 0) u = g0;
    else if (t == 1) u = 0.5f * (g0 + g1 + g2);
    else if (t == 2) u = 0.5f * (g0 - g1 + g2);
    else u = -g2;
    g_u[((size_t)((t * 3 + r) * KOUT + k)) * C_IN + c] = __float2half(u);
}

// ---------------- main kernel ----------------
// smem: 4 stages x (A 16KB [128 p2 x 128B] + B 8KB [64 k x 128B])
#define A_ST(s) ((s) * 16384u)
#define B_ST(s) (65536u + (s) * 8192u)
#define SMEM_TOTAL 98304

__device__ __forceinline__ void cp16(uint32_t dst, const void* src, uint32_t ssz) {
    asm volatile("cp.async.cg.shared.global [%0], [%1], 16, %2;"
                 :: "r"(dst), "l"(src), "r"(ssz) : "memory");
}

__device__ __forceinline__ void ldsm4(uint32_t* r, uint32_t addr) {
    asm volatile("ldmatrix.sync.aligned.m8n8.x4.shared.b16 {%0,%1,%2,%3}, [%4];"
                 : "=r"(r[0]), "=r"(r[1]), "=r"(r[2]), "=r"(r[3]) : "r"(addr));
}

__device__ __forceinline__ void mma16816(float* c, const uint32_t* a,
                                         uint32_t b0, uint32_t b1) {
    asm volatile(
        "mma.sync.aligned.m16n8k16.row.col.f32.f16.f16.f32 "
        "{%0,%1,%2,%3}, {%4,%5,%6,%7}, {%8,%9}, {%0,%1,%2,%3};"
        : "+f"(c[0]), "+f"(c[1]), "+f"(c[2]), "+f"(c[3])
        : "r"(a[0]), "r"(a[1]), "r"(a[2]), "r"(a[3]), "r"(b0), "r"(b1));
}

__global__ __launch_bounds__(256, 1) void conv_wino(float* __restrict__ out) {
    extern __shared__ char smem[];
    const uint32_t sb = su32(smem);
    const int tid = threadIdx.x;
    const int wid = tid >> 5, lane = tid & 31;
    const int wm = wid & 3, wn = wid >> 2;       // warp tile: 32m x 32n
    const unsigned p0 = blockIdx.x << 7;
    const int n0 = blockIdx.y << 6;

    // A staging coords: row = tid>>1 (128 rows x 128B), 64B half = tid&1
    const int rowT = tid >> 1, half = tid & 1;
    const unsigned p2 = p0 + rowT;
    const unsigned nImg = p2 / P2IMG;
    const unsigned rem = p2 - nImg * P2IMG;
    const int ho = (int)(rem / W2);
    // B staging coords: row = tid&63 (64 rows x 128B), 16B group base = tid>>6
    const int rowB = tid & 63, jbase = tid >> 6;

    auto issue = [&](int kc) {
        const int st = kc & 3;
        const int gg = kc / 6;
        const int sub = kc - 6 * gg;
        const int r = sub >> 1;
        const int ch0 = (sub & 1) << 6;
        const int tsel = c_ord[gg];
        // A: V_t at input row hi = ho + r - 1 (zero-fill OOB)
        const int hi = ho + r - 1;
        const bool valid = (unsigned)hi < H_IN;
        const size_t arow = valid ? (size_t)p2 + (size_t)(r - 1) * W2 : (size_t)p2;
        const uint32_t ssz = valid ? 16u : 0u;
        const __half* asrc = g_v + (size_t)tsel * VSTRIDE + arow * C_IN
                             + ch0 + half * 32;
        #pragma unroll
        for (int j = 0; j < 4; j++) {
            const uint32_t g = half * 4 + j;
            const uint32_t sw = (g ^ (rowT & 7)) << 4;
            cp16(sb + A_ST(st) + rowT * 128 + sw, asrc + j * 8, ssz);
        }
        // B: U_t[r][n0+rowB][ch0..]
        const __half* bsrc = g_u + ((size_t)((tsel * 3 + r) * KOUT + n0 + rowB)) * C_IN
                             + ch0;
        #pragma unroll
        for (int jj = 0; jj < 2; jj++) {
            const uint32_t g = jbase + jj * 4;
            const uint32_t sw = (g ^ (rowB & 7)) << 4;
            cp16(sb + B_ST(st) + rowB * 128 + sw, bsrc + g * 8, 16u);
        }
        asm volatile("cp.async.commit_group;" ::: "memory");
    };

    float y0[2][4][4], y1[2][4][4], tmp[2][4][4];
    #pragma unroll
    for (int a = 0; a < 2; a++)
        #pragma unroll
        for (int b = 0; b < 4; b++)
            #pragma unroll
            for (int c = 0; c < 4; c++) { y0[a][b][c] = 0.f; y1[a][b][c] = 0.f; }

    auto run6 = [&](int gbase, float (&acc)[2][4][4]) {
        for (int sub = 0; sub < 6; sub++) {
            const int kc = gbase * 6 + sub;
            asm volatile("cp.async.wait_group 2;" ::: "memory");
            __syncthreads();
            if (kc + 3 < NCHUNK) issue(kc + 3);
            else asm volatile("cp.async.commit_group;" ::: "memory");

            const uint32_t Ab = sb + A_ST(kc & 3);
            const uint32_t Bb = sb + B_ST(kc & 3);
            #pragma unroll
            for (int stp = 0; stp < 4; stp++) {
                uint32_t ar[2][4], br[2][4];
                #pragma unroll
                for (int mt = 0; mt < 2; mt++) {
                    const int row = wm * 32 + mt * 16 + (lane & 7) + ((lane >> 3) & 1) * 8;
                    const int grp = 2 * stp + (lane >> 4);
                    ldsm4(ar[mt], Ab + row * 128 + ((grp ^ (row & 7)) << 4));
                }
                #pragma unroll
                for (int bt = 0; bt < 2; bt++) {
                    const int row = wn * 32 + bt * 16 + (lane & 7) + (lane >> 4) * 8;
                    const int grp = 2 * stp + ((lane >> 3) & 1);
                    ldsm4(br[bt], Bb + row * 128 + ((grp ^ (row & 7)) << 4));
                }
                #pragma unroll
                for (int mt = 0; mt < 2; mt++)
                    #pragma unroll
                    for (int nt = 0; nt < 4; nt++)
                        mma16816(acc[mt][nt], ar[mt],
                                 br[nt >> 1][(nt & 1) * 2], br[nt >> 1][(nt & 1) * 2 + 1]);
            }
            __syncthreads();
        }
    };

    issue(0); issue(1); issue(2);

    run6(0, y0);   // t=0: +m0 -> y0
    run6(1, y1);   // t=3 (U negated): -m3 -> y1
    #pragma unroll
    for (int a = 0; a < 2; a++)
        #pragma unroll
        for (int b = 0; b < 4; b++)
            #pragma unroll
            for (int c = 0; c < 4; c++) tmp[a][b][c] = 0.f;
    run6(2, tmp);  // t=1: +m1
    #pragma unroll
    for (int a = 0; a < 2; a++)
        #pragma unroll
        for (int b = 0; b < 4; b++)
            #pragma unroll
            for (int c = 0; c < 4; c++) {
                y0[a][b][c] += tmp[a][b][c];
                y1[a][b][c] += tmp[a][b][c];
                tmp[a][b][c] = 0.f;
            }
    run6(3, tmp);  // t=2: +m2
    #pragma unroll
    for (int a = 0; a < 2; a++)
        #pragma unroll
        for (int b = 0; b < 4; b++)
            #pragma unroll
            for (int c = 0; c < 4; c++) {
                y0[a][b][c] += tmp[a][b][c];
                y1[a][b][c] -= tmp[a][b][c];
            }

    asm volatile("cp.async.wait_group 0;" ::: "memory");
    __syncthreads();

    // ---- epilogue: (y0,y1) -> smem float2 [64 k][130] -> coalesced pairs ----
    float2* eb2 = (float2*)smem;
    {
        const int rr = lane >> 2, cc = (lane & 3) * 2;
        #pragma unroll
        for (int mt = 0; mt < 2; mt++)
            #pragma unroll
            for (int nt = 0; nt < 4; nt++) {
                const int m = wm * 32 + mt * 16 + rr;
                const int n = wn * 32 + nt * 8 + cc;
                eb2[n * 130 + m]           = make_float2(y0[mt][nt][0], y1[mt][nt][0]);
                eb2[(n + 1) * 130 + m]     = make_float2(y0[mt][nt][1], y1[mt][nt][1]);
                eb2[n * 130 + m + 8]       = make_float2(y0[mt][nt][2], y1[mt][nt][2]);
                eb2[(n + 1) * 130 + m + 8] = make_float2(y0[mt][nt][3], y1[mt][nt][3]);
            }
    }
    __syncthreads();
    for (int j = tid; j < 64 * 128; j += 256) {
        const int k = j >> 7;
        const int m = j & 127;
        const unsigned pp = p0 + m;
        const unsigned ni = pp / P2IMG;
        const unsigned rr = pp - ni * P2IMG;
        const unsigned hh = rr / W2;
        const unsigned w2 = rr - hh * W2;
        *(float2*)(out + ((size_t)(ni * KOUT + n0 + k) * H_IN + hh) * W_IN + 2 * w2)
            = eb2[k * 130 + m];
    }
}

extern "C" void kernel_launch(void* const* d_in, const int* in_sizes, int n_in,
                              void* d_out, int out_size) {
    const float* x = (const float*)d_in[0];
    const float* w = (const float*)d_in[1];
    float* out = (float*)d_out;

    cudaFuncSetAttribute(conv_wino, cudaFuncAttributeMaxDynamicSharedMemorySize,
                         SMEM_TOTAL);

    dim3 gx(H_IN, NIMG);
    prep_xw<<<gx, 256>>>(x);
    prep_wu<<<(4 * 3 * KOUT * C_IN + 255) / 256, 256>>>(w);
    dim3 grid(P2TOT / 128, KOUT / 64);
    conv_wino<<<grid, 256, SMEM_TOTAL>>>(out);
}